// round 1
// baseline (speedup 1.0000x reference)
#include <cuda_runtime.h>
#include <cuda_bf16.h>

#define NBINS 10

// Global accumulators (scratch — no device allocation allowed).
__device__ float g_sums[NBINS];
__device__ float g_cnts[NBINS];

__global__ void ghmc_init_bins() {
    int i = threadIdx.x;
    if (i < NBINS) {
        g_sums[i] = 0.0f;
        g_cnts[i] = 0.0f;
    }
}

__global__ __launch_bounds__(256) void ghmc_main(
    const float4* __restrict__ pred4,
    const int4*   __restrict__ targ4,
    const float4* __restrict__ lw4,
    long n4)
{
    float s[NBINS];
    float c[NBINS];
#pragma unroll
    for (int b = 0; b < NBINS; b++) { s[b] = 0.0f; c[b] = 0.0f; }

    const long stride = (long)gridDim.x * blockDim.x;
    for (long i = (long)blockIdx.x * blockDim.x + threadIdx.x; i < n4; i += stride) {
        float4 p = pred4[i];
        int4   t = targ4[i];
        float4 w = lw4[i];

        float px[4] = {p.x, p.y, p.z, p.w};
        int   tx[4] = {t.x, t.y, t.z, t.w};
        float wx[4] = {w.x, w.y, w.z, w.w};

#pragma unroll
        for (int k = 0; k < 4; k++) {
            float x  = px[k];
            float tf = (float)tx[k];
            bool  valid = wx[k] > 0.0f;

            float a = fabsf(x);
            float e = __expf(-a);            // exp(-|x|) in (0,1]
            float r = __fdividef(1.0f, 1.0f + e);  // 1/(1+e) = sigmoid(|x|)

            // g = |sigmoid(x) - t| = sigmoid(x * (1-2t)):
            //   x' = (t==1) ? -x : x ;  g = (x'>=0) ? r : e*r
            float xp = (tx[k] != 0) ? -x : x;
            float g  = (xp >= 0.0f) ? r : e * r;

            int bin = (int)(g * 10.0f);      // truncation, g in [0,1]
            bin = min(bin, NBINS - 1);

            // bce = max(x,0) - x*t + log1p(exp(-|x|));  log(1+e) = -log(r)
            float bce = fmaxf(x, 0.0f) - x * tf - __logf(r);

            float v  = valid ? bce : 0.0f;
            float cf = valid ? 1.0f : 0.0f;

#pragma unroll
            for (int b = 0; b < NBINS; b++) {
                bool hit = (bin == b);
                s[b] = hit ? s[b] + v  : s[b];
                c[b] = hit ? c[b] + cf : c[b];
            }
        }
    }

    // Warp butterfly reduce all 20 accumulators.
    const unsigned full = 0xffffffffu;
#pragma unroll
    for (int b = 0; b < NBINS; b++) {
#pragma unroll
        for (int o = 16; o > 0; o >>= 1) {
            s[b] += __shfl_down_sync(full, s[b], o);
            c[b] += __shfl_down_sync(full, c[b], o);
        }
    }

    __shared__ float sh_s[NBINS];
    __shared__ float sh_c[NBINS];
    if (threadIdx.x < NBINS) {
        sh_s[threadIdx.x] = 0.0f;
        sh_c[threadIdx.x] = 0.0f;
    }
    __syncthreads();

    if ((threadIdx.x & 31) == 0) {
#pragma unroll
        for (int b = 0; b < NBINS; b++) {
            atomicAdd(&sh_s[b], s[b]);
            atomicAdd(&sh_c[b], c[b]);
        }
    }
    __syncthreads();

    if (threadIdx.x < NBINS) {
        atomicAdd(&g_sums[threadIdx.x], sh_s[threadIdx.x]);
        atomicAdd(&g_cnts[threadIdx.x], sh_c[threadIdx.x]);
    }
}

__global__ void ghmc_finalize(float* __restrict__ out) {
    int i = threadIdx.x;
    float contrib = 0.0f;
    float nb = 0.0f;
    if (i < NBINS) {
        float cb = g_cnts[i];
        float sb = g_sums[i];
        contrib = sb / fmaxf(cb, 1.0f);   // empty bins have sb==0 -> contrib 0
        nb = (cb > 0.0f) ? 1.0f : 0.0f;
    }
#pragma unroll
    for (int o = 16; o > 0; o >>= 1) {
        contrib += __shfl_down_sync(0xffffffffu, contrib, o);
        nb      += __shfl_down_sync(0xffffffffu, nb, o);
    }
    if (i == 0) {
        // loss = (1/n) * sum_b S_b / max(c_b,1); LOSS_WEIGHT = 1.0
        out[0] = contrib / fmaxf(nb, 1.0f);
    }
}

extern "C" void kernel_launch(void* const* d_in, const int* in_sizes, int n_in,
                              void* d_out, int out_size) {
    const float4* pred4 = (const float4*)d_in[0];
    const int4*   targ4 = (const int4*)d_in[1];
    const float4* lw4   = (const float4*)d_in[2];
    float* out = (float*)d_out;

    long n  = (long)in_sizes[0];
    long n4 = n >> 2;   // N*C = 67,108,864 divisible by 4

    ghmc_init_bins<<<1, 32>>>();
    ghmc_main<<<1184, 256>>>(pred4, targ4, lw4, n4);
    ghmc_finalize<<<1, 32>>>(out);
}